// round 13
// baseline (speedup 1.0000x reference)
#include <cuda_runtime.h>

// Problem constants (fixed by setup_inputs)
#define NB 16
#define H 768
#define W 768
#define HW (H * W)          // 589824
#define NHW (NB * HW)       // 9437184

#define T 256
#define GBLKS (HW / T)               // 2304  (1 px/thread, proven fastest shape)
#define PBLKS (HW / (T * 4))         // 576   (prepass, 4 px/thread streaming)

// Ping-pong scratch for interleaved disp (float2 = (dx, dy)) — static, no alloc.
__device__ float2 g_bufA[NHW];
__device__ float2 g_bufB[NHW];

__device__ __forceinline__ int clampi(int v, int hi) {
    return min(max(v, 0), hi);
}

// ---------------------------------------------------------------------------
// Prepass: planar pred_disp [N,2,H,W] -> interleaved float2; zero num_touch;
// write the constant pred_cent b-plane (= n). Pure streaming.
// ---------------------------------------------------------------------------
__global__ __launch_bounds__(T, 8)
void interleave(const float* __restrict__ in, float2* __restrict__ out,
                float* __restrict__ nt, float* __restrict__ pc_b) {
    const int p = (blockIdx.x * T + threadIdx.x) * 4;
    const int n = blockIdx.y;

    const float* base = in + (size_t)n * 2 * HW;
    const float4 vx = *(const float4*)(base + p);
    const float4 vy = *(const float4*)(base + HW + p);

    float2* ob = out + (size_t)n * HW + p;
    *(float4*)(ob)     = make_float4(vx.x, vy.x, vx.y, vy.y);
    *(float4*)(ob + 2) = make_float4(vx.z, vy.z, vx.w, vy.w);

    __stcs((float4*)(nt + (size_t)n * HW + p), make_float4(0.f, 0.f, 0.f, 0.f));
    __stcs((float4*)(pc_b + (size_t)n * 3 * HW + p),
           make_float4((float)n, (float)n, (float)n, (float)n));

    cudaTriggerProgrammaticLaunchCompletion();
}

// ---------------------------------------------------------------------------
// Iterations 1,2,3: interleaved -> interleaved. 1 px/thread — empirically the
// fastest shape (53.5us): max warps, min regs, smallest L1tex queue batches.
// ---------------------------------------------------------------------------
__global__ __launch_bounds__(T, 8)
void iter_mid(const float2* __restrict__ in, float2* __restrict__ out) {
    const int p = blockIdx.x * T + threadIdx.x;
    const int n = blockIdx.y;
    const int y = p / W;
    const int x = p - y * W;
    const float2* base = in + (size_t)n * HW;

    cudaGridDependencySynchronize();   // PDL: wait for producer's data

    const float2 d = base[p];

    const int cx = clampi((int)((float)x + d.x), W - 1);
    const int cy = clampi((int)((float)y + d.y), H - 1);

    const float2 g = __ldg(base + cy * W + cx);

    out[(size_t)n * HW + p] = make_float2(d.x + g.x, d.y + g.y);

    cudaTriggerProgrammaticLaunchCompletion();
}

// ---------------------------------------------------------------------------
// Iteration 4 (final): gather + planar disp out + num_touch scatter-add +
// pred_cent cx/cy planes (b-plane written by prepass). 1 px/thread.
//   d_out layout: [disp: 2*NHW][num_touch: NHW][pred_cent: 3*NHW]
// ---------------------------------------------------------------------------
__global__ __launch_bounds__(T, 8)
void iter_last(const float2* __restrict__ in,
               float* __restrict__ disp_out,
               float* __restrict__ nt_out,
               float* __restrict__ pc_out) {
    const int p = blockIdx.x * T + threadIdx.x;
    const int n = blockIdx.y;
    const int y = p / W;
    const int x = p - y * W;
    const float2* base = in + (size_t)n * HW;

    cudaGridDependencySynchronize();   // PDL: wait for iter-3 data

    const float2 d = base[p];

    const int cx = clampi((int)((float)x + d.x), W - 1);
    const int cy = clampi((int)((float)y + d.y), H - 1);
    const int gp = cy * W + cx;

    // Issue the gather first...
    const float2 g = __ldg(base + gp);

    // ...then work that does not consume it (overlaps gather latency):
    atomicAdd(&nt_out[(size_t)n * HW + gp], 1.0f);   // fire-and-forget RED

    float* pb = pc_out + (size_t)n * 3 * HW;
    __stcs(pb + HW + p,     (float)cx);
    __stcs(pb + 2 * HW + p, (float)cy);

    // Gather consumers last: disp out (planar [N,2,H,W]) — streaming
    float* db = disp_out + (size_t)n * 2 * HW;
    __stcs(db + p,      d.x + g.x);
    __stcs(db + HW + p, d.y + g.y);
}

// ---------------------------------------------------------------------------
// Host: PDL launches so each kernel's prologue overlaps its producer's tail.
// ---------------------------------------------------------------------------
template <typename K, typename... Args>
static inline void launch_pdl(K kernel, dim3 grid, dim3 block, Args... args) {
    cudaLaunchConfig_t cfg = {};
    cfg.gridDim = grid;
    cfg.blockDim = block;
    cfg.stream = 0;
    cudaLaunchAttribute at[1];
    at[0].id = cudaLaunchAttributeProgrammaticStreamSerialization;
    at[0].val.programmaticStreamSerializationAllowed = 1;
    cfg.attrs = at;
    cfg.numAttrs = 1;
    cudaLaunchKernelEx(&cfg, kernel, args...);
}

extern "C" void kernel_launch(void* const* d_in, const int* in_sizes, int n_in,
                              void* d_out, int out_size) {
    const float* pred_disp = (const float*)d_in[0];
    float* out = (float*)d_out;

    float* disp_out = out;                      // 2*NHW
    float* nt_out   = out + (size_t)2 * NHW;    // NHW
    float* pc_out   = out + (size_t)3 * NHW;    // 3*NHW

    float2* bufA;  cudaGetSymbolAddress((void**)&bufA, g_bufA);
    float2* bufB;  cudaGetSymbolAddress((void**)&bufB, g_bufB);

    dim3 pgrid(PBLKS, NB);
    dim3 ggrid(GBLKS, NB);

    interleave<<<pgrid, T>>>(pred_disp, bufA, nt_out, pc_out);          // prepass
    launch_pdl(iter_mid,  ggrid, dim3(T), (const float2*)bufA, bufB);   // it 1
    launch_pdl(iter_mid,  ggrid, dim3(T), (const float2*)bufB, bufA);   // it 2
    launch_pdl(iter_mid,  ggrid, dim3(T), (const float2*)bufA, bufB);   // it 3
    launch_pdl(iter_last, ggrid, dim3(T), (const float2*)bufB,
               disp_out, nt_out, pc_out);                               // it 4
}

// round 14
// speedup vs baseline: 1.0279x; 1.0279x over previous
#include <cuda_runtime.h>

// Problem constants (fixed by setup_inputs)
#define NB 16
#define H 768
#define W 768
#define HW (H * W)          // 589824
#define NHW (NB * HW)       // 9437184

#define T 256
#define MBLKS (HW / T)               // 2304  (iter_mid: 1 px/thread — fastest)
#define LBLKS (HW / (T * 4))         // 576   (iter_last + prepass: 4 px/thread)

// Ping-pong scratch for interleaved disp (float2 = (dx, dy)) — static, no alloc.
__device__ float2 g_bufA[NHW];
__device__ float2 g_bufB[NHW];

__device__ __forceinline__ int clampi(int v, int hi) {
    return min(max(v, 0), hi);
}

// ---------------------------------------------------------------------------
// Prepass: planar pred_disp [N,2,H,W] -> interleaved float2; zero num_touch;
// write the constant pred_cent b-plane (= n). Pure streaming, 4 px/thread.
// ---------------------------------------------------------------------------
__global__ __launch_bounds__(T, 8)
void interleave(const float* __restrict__ in, float2* __restrict__ out,
                float* __restrict__ nt, float* __restrict__ pc_b) {
    const int p = (blockIdx.x * T + threadIdx.x) * 4;
    const int n = blockIdx.y;

    const float* base = in + (size_t)n * 2 * HW;
    const float4 vx = *(const float4*)(base + p);
    const float4 vy = *(const float4*)(base + HW + p);

    float2* ob = out + (size_t)n * HW + p;
    *(float4*)(ob)     = make_float4(vx.x, vy.x, vx.y, vy.y);
    *(float4*)(ob + 2) = make_float4(vx.z, vy.z, vx.w, vy.w);

    __stcs((float4*)(nt + (size_t)n * HW + p), make_float4(0.f, 0.f, 0.f, 0.f));
    __stcs((float4*)(pc_b + (size_t)n * 3 * HW + p),
           make_float4((float)n, (float)n, (float)n, (float)n));

    cudaTriggerProgrammaticLaunchCompletion();
}

// ---------------------------------------------------------------------------
// Iterations 1,2,3: interleaved -> interleaved. 1 px/thread — measured fastest
// shape (53.5us): max warps, min regs, smallest L1tex queue batches.
// ---------------------------------------------------------------------------
__global__ __launch_bounds__(T, 8)
void iter_mid(const float2* __restrict__ in, float2* __restrict__ out) {
    const int p = blockIdx.x * T + threadIdx.x;
    const int n = blockIdx.y;
    const int y = p / W;
    const int x = p - y * W;
    const float2* base = in + (size_t)n * HW;

    cudaGridDependencySynchronize();   // PDL: wait for producer's data

    const float2 d = base[p];

    const int cx = clampi((int)((float)x + d.x), W - 1);
    const int cy = clampi((int)((float)y + d.y), H - 1);

    const float2 g = __ldg(base + cy * W + cx);

    out[(size_t)n * HW + p] = make_float2(d.x + g.x, d.y + g.y);

    cudaTriggerProgrammaticLaunchCompletion();
}

// ---------------------------------------------------------------------------
// Iteration 4 (final): 4 px/thread — measured fastest shape for the
// store/atomic-heavy pass (vectorized stcs stores, batched REDs).
//   d_out layout: [disp: 2*NHW][num_touch: NHW][pred_cent: 3*NHW]
// ---------------------------------------------------------------------------
__global__ __launch_bounds__(T, 8)
void iter_last(const float2* __restrict__ in,
               float* __restrict__ disp_out,
               float* __restrict__ nt_out,
               float* __restrict__ pc_out) {
    const int p = (blockIdx.x * T + threadIdx.x) * 4;
    const int n = blockIdx.y;
    const int y = p / W;
    const int x = p - y * W;
    const float2* base = in + (size_t)n * HW;

    cudaGridDependencySynchronize();   // PDL: wait for iter-3 data

    const float4 a = *(const float4*)(base + p);
    const float4 b = *(const float4*)(base + p + 2);
    float dx[4] = {a.x, a.z, b.x, b.z};
    float dy[4] = {a.y, a.w, b.y, b.w};

    int cx[4], cy[4], gp[4];
#pragma unroll
    for (int i = 0; i < 4; i++) {
        cx[i] = clampi((int)((float)(x + i) + dx[i]), W - 1);
        cy[i] = clampi((int)((float)y + dy[i]), H - 1);
        gp[i] = cy[i] * W + cx[i];
    }

    // Issue the 4 independent gathers first...
    float2 g[4];
#pragma unroll
    for (int i = 0; i < 4; i++) g[i] = __ldg(base + gp[i]);

    // ...then work that does not consume them (overlaps gather latency):
    float* ntb = nt_out + (size_t)n * HW;
#pragma unroll
    for (int i = 0; i < 4; i++) atomicAdd(&ntb[gp[i]], 1.0f);  // RED, exact in f32

    float* pb = pc_out + (size_t)n * 3 * HW;
    __stcs((float4*)(pb + HW + p), make_float4((float)cx[0], (float)cx[1],
                                               (float)cx[2], (float)cx[3]));
    __stcs((float4*)(pb + 2 * HW + p), make_float4((float)cy[0], (float)cy[1],
                                                   (float)cy[2], (float)cy[3]));

    // Gather consumers last: disp out (planar [N,2,H,W]) — streaming
    float* db = disp_out + (size_t)n * 2 * HW;
    __stcs((float4*)(db + p),      make_float4(dx[0] + g[0].x, dx[1] + g[1].x,
                                               dx[2] + g[2].x, dx[3] + g[3].x));
    __stcs((float4*)(db + HW + p), make_float4(dy[0] + g[0].y, dy[1] + g[1].y,
                                               dy[2] + g[2].y, dy[3] + g[3].y));
}

// ---------------------------------------------------------------------------
// Host: PDL launches so each kernel's prologue overlaps its producer's tail.
// ---------------------------------------------------------------------------
template <typename K, typename... Args>
static inline void launch_pdl(K kernel, dim3 grid, dim3 block, Args... args) {
    cudaLaunchConfig_t cfg = {};
    cfg.gridDim = grid;
    cfg.blockDim = block;
    cfg.stream = 0;
    cudaLaunchAttribute at[1];
    at[0].id = cudaLaunchAttributeProgrammaticStreamSerialization;
    at[0].val.programmaticStreamSerializationAllowed = 1;
    cfg.attrs = at;
    cfg.numAttrs = 1;
    cudaLaunchKernelEx(&cfg, kernel, args...);
}

extern "C" void kernel_launch(void* const* d_in, const int* in_sizes, int n_in,
                              void* d_out, int out_size) {
    const float* pred_disp = (const float*)d_in[0];
    float* out = (float*)d_out;

    float* disp_out = out;                      // 2*NHW
    float* nt_out   = out + (size_t)2 * NHW;    // NHW
    float* pc_out   = out + (size_t)3 * NHW;    // 3*NHW

    float2* bufA;  cudaGetSymbolAddress((void**)&bufA, g_bufA);
    float2* bufB;  cudaGetSymbolAddress((void**)&bufB, g_bufB);

    dim3 pgrid(LBLKS, NB);
    dim3 mgrid(MBLKS, NB);

    interleave<<<pgrid, T>>>(pred_disp, bufA, nt_out, pc_out);          // prepass
    launch_pdl(iter_mid,  mgrid, dim3(T), (const float2*)bufA, bufB);   // it 1
    launch_pdl(iter_mid,  mgrid, dim3(T), (const float2*)bufB, bufA);   // it 2
    launch_pdl(iter_mid,  mgrid, dim3(T), (const float2*)bufA, bufB);   // it 3
    launch_pdl(iter_last, pgrid, dim3(T), (const float2*)bufB,
               disp_out, nt_out, pc_out);                               // it 4
}

// round 15
// speedup vs baseline: 1.0560x; 1.0273x over previous
#include <cuda_runtime.h>

// Problem constants (fixed by setup_inputs)
#define NB 16
#define H 768
#define W 768
#define HW (H * W)          // 589824
#define NHW (NB * HW)       // 9437184

#define T 256
#define MBLKS (HW / (T * 2))         // 1152  (iter_mid: 2 px/thread)
#define LBLKS (HW / (T * 4))         // 576   (iter_last + prepass: 4 px/thread)

// Ping-pong scratch for interleaved disp (float2 = (dx, dy)) — static, no alloc.
__device__ float2 g_bufA[NHW];
__device__ float2 g_bufB[NHW];

__device__ __forceinline__ int clampi(int v, int hi) {
    return min(max(v, 0), hi);
}

// ---------------------------------------------------------------------------
// Prepass: planar pred_disp [N,2,H,W] -> interleaved float2; zero num_touch;
// write the constant pred_cent b-plane (= n). Pure streaming, 4 px/thread.
// ---------------------------------------------------------------------------
__global__ __launch_bounds__(T, 8)
void interleave(const float* __restrict__ in, float2* __restrict__ out,
                float* __restrict__ nt, float* __restrict__ pc_b) {
    const int p = (blockIdx.x * T + threadIdx.x) * 4;
    const int n = blockIdx.y;

    const float* base = in + (size_t)n * 2 * HW;
    const float4 vx = *(const float4*)(base + p);
    const float4 vy = *(const float4*)(base + HW + p);

    float2* ob = out + (size_t)n * HW + p;
    *(float4*)(ob)     = make_float4(vx.x, vy.x, vx.y, vy.y);
    *(float4*)(ob + 2) = make_float4(vx.z, vy.z, vx.w, vy.w);

    __stcs((float4*)(nt + (size_t)n * HW + p), make_float4(0.f, 0.f, 0.f, 0.f));
    __stcs((float4*)(pc_b + (size_t)n * 3 * HW + p),
           make_float4((float)n, (float)n, (float)n, (float)n));

    cudaTriggerProgrammaticLaunchCompletion();
}

// ---------------------------------------------------------------------------
// Iterations 1,2,3: interleaved -> interleaved. 2 px/thread: one LDG.128 in,
// two independent scattered LDG.64 gathers, one STG.128 out. Minimal issue
// slots for coalesced ops while keeping gather batches small.
// ---------------------------------------------------------------------------
__global__ __launch_bounds__(T, 8)
void iter_mid(const float2* __restrict__ in, float2* __restrict__ out) {
    const int p = (blockIdx.x * T + threadIdx.x) * 2;   // W%2==0: same row
    const int n = blockIdx.y;
    const int y = p / W;
    const int x = p - y * W;
    const float2* base = in + (size_t)n * HW;

    cudaGridDependencySynchronize();   // PDL: wait for producer's data

    const float4 v = *(const float4*)(base + p);   // px0 = (v.x,v.y), px1 = (v.z,v.w)

    const int cx0 = clampi((int)((float)x + v.x), W - 1);
    const int cy0 = clampi((int)((float)y + v.y), H - 1);
    const int cx1 = clampi((int)((float)(x + 1) + v.z), W - 1);
    const int cy1 = clampi((int)((float)y + v.w), H - 1);

    const float2 g0 = __ldg(base + cy0 * W + cx0);
    const float2 g1 = __ldg(base + cy1 * W + cx1);

    *(float4*)(out + (size_t)n * HW + p) =
        make_float4(v.x + g0.x, v.y + g0.y, v.z + g1.x, v.w + g1.y);

    cudaTriggerProgrammaticLaunchCompletion();
}

// ---------------------------------------------------------------------------
// Iteration 4 (final): 4 px/thread — measured fastest shape for the
// store/atomic-heavy pass (vectorized stcs stores, batched REDs).
//   d_out layout: [disp: 2*NHW][num_touch: NHW][pred_cent: 3*NHW]
// ---------------------------------------------------------------------------
__global__ __launch_bounds__(T, 8)
void iter_last(const float2* __restrict__ in,
               float* __restrict__ disp_out,
               float* __restrict__ nt_out,
               float* __restrict__ pc_out) {
    const int p = (blockIdx.x * T + threadIdx.x) * 4;
    const int n = blockIdx.y;
    const int y = p / W;
    const int x = p - y * W;
    const float2* base = in + (size_t)n * HW;

    cudaGridDependencySynchronize();   // PDL: wait for iter-3 data

    const float4 a = *(const float4*)(base + p);
    const float4 b = *(const float4*)(base + p + 2);
    float dx[4] = {a.x, a.z, b.x, b.z};
    float dy[4] = {a.y, a.w, b.y, b.w};

    int cx[4], cy[4], gp[4];
#pragma unroll
    for (int i = 0; i < 4; i++) {
        cx[i] = clampi((int)((float)(x + i) + dx[i]), W - 1);
        cy[i] = clampi((int)((float)y + dy[i]), H - 1);
        gp[i] = cy[i] * W + cx[i];
    }

    // Issue the 4 independent gathers first...
    float2 g[4];
#pragma unroll
    for (int i = 0; i < 4; i++) g[i] = __ldg(base + gp[i]);

    // ...then work that does not consume them (overlaps gather latency):
    float* ntb = nt_out + (size_t)n * HW;
#pragma unroll
    for (int i = 0; i < 4; i++) atomicAdd(&ntb[gp[i]], 1.0f);  // RED, exact in f32

    float* pb = pc_out + (size_t)n * 3 * HW;
    __stcs((float4*)(pb + HW + p), make_float4((float)cx[0], (float)cx[1],
                                               (float)cx[2], (float)cx[3]));
    __stcs((float4*)(pb + 2 * HW + p), make_float4((float)cy[0], (float)cy[1],
                                                   (float)cy[2], (float)cy[3]));

    // Gather consumers last: disp out (planar [N,2,H,W]) — streaming
    float* db = disp_out + (size_t)n * 2 * HW;
    __stcs((float4*)(db + p),      make_float4(dx[0] + g[0].x, dx[1] + g[1].x,
                                               dx[2] + g[2].x, dx[3] + g[3].x));
    __stcs((float4*)(db + HW + p), make_float4(dy[0] + g[0].y, dy[1] + g[1].y,
                                               dy[2] + g[2].y, dy[3] + g[3].y));
}

// ---------------------------------------------------------------------------
// Host: PDL launches so each kernel's prologue overlaps its producer's tail.
// ---------------------------------------------------------------------------
template <typename K, typename... Args>
static inline void launch_pdl(K kernel, dim3 grid, dim3 block, Args... args) {
    cudaLaunchConfig_t cfg = {};
    cfg.gridDim = grid;
    cfg.blockDim = block;
    cfg.stream = 0;
    cudaLaunchAttribute at[1];
    at[0].id = cudaLaunchAttributeProgrammaticStreamSerialization;
    at[0].val.programmaticStreamSerializationAllowed = 1;
    cfg.attrs = at;
    cfg.numAttrs = 1;
    cudaLaunchKernelEx(&cfg, kernel, args...);
}

extern "C" void kernel_launch(void* const* d_in, const int* in_sizes, int n_in,
                              void* d_out, int out_size) {
    const float* pred_disp = (const float*)d_in[0];
    float* out = (float*)d_out;

    float* disp_out = out;                      // 2*NHW
    float* nt_out   = out + (size_t)2 * NHW;    // NHW
    float* pc_out   = out + (size_t)3 * NHW;    // 3*NHW

    float2* bufA;  cudaGetSymbolAddress((void**)&bufA, g_bufA);
    float2* bufB;  cudaGetSymbolAddress((void**)&bufB, g_bufB);

    dim3 pgrid(LBLKS, NB);
    dim3 mgrid(MBLKS, NB);

    interleave<<<pgrid, T>>>(pred_disp, bufA, nt_out, pc_out);          // prepass
    launch_pdl(iter_mid,  mgrid, dim3(T), (const float2*)bufA, bufB);   // it 1
    launch_pdl(iter_mid,  mgrid, dim3(T), (const float2*)bufB, bufA);   // it 2
    launch_pdl(iter_mid,  mgrid, dim3(T), (const float2*)bufA, bufB);   // it 3
    launch_pdl(iter_last, pgrid, dim3(T), (const float2*)bufB,
               disp_out, nt_out, pc_out);                               // it 4
}